// round 11
// baseline (speedup 1.0000x reference)
#include <cuda_runtime.h>
#include <cuda_bf16.h>
#include <stdint.h>

// Problem constants
#define NN      8192
#define KIN     256
#define OD      64
#define HD      128          // HEADS*OUT_DIM
#define NP      144          // padded GEMM N (multiple of 16 >= 130)
#define NB      130          // real B rows: 128 value cols + 2 denominator cols
#define MT      256          // M rows per CTA
#define KC      32           // K chunk per pipeline stage
#define KSPLIT  4
#define KLEN    (NN/KSPLIT)  // 2048
#define NCHUNK  (KLEN/KC)    // 64
#define NMT     (NN/MT)      // 32

// ---------------- device scratch (no runtime allocation allowed) ----------------
__device__ float          g_h[NN*HD];                 // 4 MB    h = x @ W^T
__device__ float          g_w[NN*2];                  // exp(er) per node/head
__device__ __nv_bfloat16  g_Bhi[NP*NN];               // 2.36 MB B hi, [n][j]; rows 130..143 stay 0
__device__ __nv_bfloat16  g_Blo[NP*NN];               // 2.36 MB B lo
__device__ float          g_part[KSPLIT*NMT*MT*NP];   // 18.9 MB K-split partials

// ---------------- helpers ----------------
__device__ __forceinline__ uint32_t smem_u32(const void* p) {
    uint32_t a;
    asm("{ .reg .u64 t; cvta.to.shared.u64 t, %1; cvt.u32.u64 %0, t; }" : "=r"(a) : "l"(p));
    return a;
}
// SW64 swizzle for 64-byte rows: XOR 16B-unit index (bits 4:5) with row bits (o bits 7:8)
#define SWZ64(o) ((o) ^ (((o) >> 3) & 0x30))

__device__ __forceinline__ void ldsm_x4(uint32_t& r0, uint32_t& r1, uint32_t& r2, uint32_t& r3,
                                        uint32_t addr) {
    asm volatile("ldmatrix.sync.aligned.m8n8.x4.shared.b16 {%0,%1,%2,%3}, [%4];"
                 : "=r"(r0), "=r"(r1), "=r"(r2), "=r"(r3) : "r"(addr));
}
__device__ __forceinline__ void ldsm_x2(uint32_t& r0, uint32_t& r1, uint32_t addr) {
    asm volatile("ldmatrix.sync.aligned.m8n8.x2.shared.b16 {%0,%1}, [%2];"
                 : "=r"(r0), "=r"(r1) : "r"(addr));
}
// D(fp32) += A(bf16 row) * B(bf16 col) ; m16n8k16
__device__ __forceinline__ void mma_bf16(float* c, uint32_t a0, uint32_t a1, uint32_t a2,
                                         uint32_t a3, uint32_t b0, uint32_t b1) {
    asm volatile("mma.sync.aligned.m16n8k16.row.col.f32.bf16.bf16.f32 "
                 "{%0,%1,%2,%3}, {%4,%5,%6,%7}, {%8,%9}, {%0,%1,%2,%3};"
                 : "+f"(c[0]), "+f"(c[1]), "+f"(c[2]), "+f"(c[3])
                 : "r"(a0), "r"(a1), "r"(a2), "r"(a3), "r"(b0), "r"(b1));
}
#define CP_ASYNC16(dst, src) \
    asm volatile("cp.async.cg.shared.global [%0], [%1], 16;" :: "r"(dst), "l"(src))
#define CP_COMMIT() asm volatile("cp.async.commit_group;")
#define CP_WAIT0()  asm volatile("cp.async.wait_group 0;")

// ---------------- K1: h = x @ W^T  (fp32, tiled) ----------------
__global__ __launch_bounds__(256) void k1_gemm(const float* __restrict__ x,
                                               const float* __restrict__ W) {
    __shared__ float As[16][64];    // [k][row]
    __shared__ float Bs[16][128];   // [k][col]
    const int t = threadIdx.x;
    const int i0 = blockIdx.x * 64;
    const int tr = t >> 5, tc = t & 31;
    float acc[8][4] = {};

    for (int kt = 0; kt < KIN; kt += 16) {
        {   // x tile 64x16
            int r = t >> 2, kg = (t & 3) * 4;
            float4 v = *(const float4*)(x + (size_t)(i0 + r) * KIN + kt + kg);
            As[kg + 0][r] = v.x; As[kg + 1][r] = v.y; As[kg + 2][r] = v.z; As[kg + 3][r] = v.w;
        }
        {   // W tile transposed
            int n = t >> 1, kg = (t & 1) * 8;
            float4 v0 = *(const float4*)(W + (size_t)n * KIN + kt + kg);
            float4 v1 = *(const float4*)(W + (size_t)n * KIN + kt + kg + 4);
            Bs[kg + 0][n] = v0.x; Bs[kg + 1][n] = v0.y; Bs[kg + 2][n] = v0.z; Bs[kg + 3][n] = v0.w;
            Bs[kg + 4][n] = v1.x; Bs[kg + 5][n] = v1.y; Bs[kg + 6][n] = v1.z; Bs[kg + 7][n] = v1.w;
        }
        __syncthreads();
#pragma unroll
        for (int kk = 0; kk < 16; kk++) {
            float4 a0 = *(float4*)&As[kk][tr * 8];
            float4 a1 = *(float4*)&As[kk][tr * 8 + 4];
            float a[8] = {a0.x, a0.y, a0.z, a0.w, a1.x, a1.y, a1.z, a1.w};
            float b[4];
#pragma unroll
            for (int cc = 0; cc < 4; cc++) b[cc] = Bs[kk][tc + 32 * cc];
#pragma unroll
            for (int rr = 0; rr < 8; rr++)
#pragma unroll
                for (int cc = 0; cc < 4; cc++)
                    acc[rr][cc] = fmaf(a[rr], b[cc], acc[rr][cc]);
        }
        __syncthreads();
    }
#pragma unroll
    for (int rr = 0; rr < 8; rr++)
#pragma unroll
        for (int cc = 0; cc < 4; cc++)
            g_h[(size_t)(i0 + tr * 8 + rr) * HD + tc + 32 * cc] = acc[rr][cc];
}

// ---------------- K1b-a: w[j,h] = exp(er[j,h])  (attn_l cancels in the j-softmax) ----------------
__global__ __launch_bounds__(256) void k1b_er(const float* __restrict__ attn_r) {
    const int j = blockIdx.x * 8 + (threadIdx.x >> 5);
    const int l = threadIdx.x & 31;
    float4 hv = *(const float4*)(g_h + (size_t)j * HD + l * 4);
    const float* h4 = (const float*)&hv;
    const int head = l >> 4;
    float p = 0.f;
#pragma unroll
    for (int q = 0; q < 4; q++)
        p = fmaf(h4[q], attn_r[head * OD + ((l * 4 + q) & 63)], p);
    float p0 = head ? 0.f : p;
    float p1 = head ? p : 0.f;
#pragma unroll
    for (int off = 16; off; off >>= 1) {
        p0 += __shfl_xor_sync(0xFFFFFFFFu, p0, off);
        p1 += __shfl_xor_sync(0xFFFFFFFFu, p1, off);
    }
    if (l == 0) {
        g_w[j * 2 + 0] = expf(p0);
        g_w[j * 2 + 1] = expf(p1);
    }
}

// ---------------- K1b-b: split-bf16 B via smem transpose (coalesced both sides) ----------------
// block: 64 nodes x all 130 rows; read g_h rows coalesced, write B rows coalesced along j
__global__ __launch_bounds__(256) void k1b_buildB() {
    __shared__ float sh[64][129];   // padded stride (odd) -> conflict-free column reads
    __shared__ float sw[64][2];
    const int t = threadIdx.x;
    const int j0 = blockIdx.x * 64;
#pragma unroll
    for (int it = 0; it < 8; it++) {
        int idx = t + it * 256;            // 2048 float4 = 64 rows x 32 f4
        int r = idx >> 5, c4 = idx & 31;
        float4 v = *(const float4*)(g_h + (size_t)(j0 + r) * HD + c4 * 4);
        sh[r][c4 * 4 + 0] = v.x; sh[r][c4 * 4 + 1] = v.y;
        sh[r][c4 * 4 + 2] = v.z; sh[r][c4 * 4 + 3] = v.w;
    }
    if (t < 128) sw[t >> 1][t & 1] = g_w[(j0 + (t >> 1)) * 2 + (t & 1)];
    __syncthreads();

    const int j = t & 63, cq = t >> 6;     // 4 B-rows x 64 nodes per iteration
#pragma unroll 4
    for (int cb = 0; cb < 132; cb += 4) {
        int c = cb + cq;
        if (c < NB) {
            float v = (c < HD) ? sw[j][c >> 6] * sh[j][c] : sw[j][c - HD];
            __nv_bfloat16 hi = __float2bfloat16_rn(v);
            g_Bhi[(size_t)c * NN + j0 + j] = hi;
            g_Blo[(size_t)c * NN + j0 + j] = __float2bfloat16_rn(v - __bfloat162float(hi));
        }
    }
}

// ---------------- K2: adj @ [Bhi|Blo]^T ; warp tile 32x72, cp.async B, SW64 64B rows ----------
// stage layout: A 256x32 bf16 (64B rows) = 16384 ; Bhi 144x32 = 9216 ; Blo 9216 -> 34816
#define SA_OFF   0
#define SH_OFF   16384
#define SL_OFF   25600
#define STG      34816
#define SMEM_K2  (2 * STG)     // 69632

__global__ __launch_bounds__(512, 1)
void k2_agg(const int* __restrict__ adj) {
    extern __shared__ char smem[];
    const uint32_t sb = smem_u32(smem);
    const int t = threadIdx.x, wid = t >> 5, l = t & 31;
    const int mt = blockIdx.x & (NMT - 1), ks = blockIdx.x >> 5;
    const int i0 = mt * MT;
    const int kbase = ks * KLEN;

    // warp grid 8M x 2N ; warp tile 32(M) x 72(N)
    const int mb = (wid >> 1) * 32;
    const int nb = (wid & 1) * 72;
    const int lm = l & 15;
    const int brow  = (l & 7) + ((l >> 4) << 3);
    const int bhalf = (l >> 3) & 1;

    float acc[18][4];
#pragma unroll
    for (int u = 0; u < 18; u++)
#pragma unroll
        for (int q = 0; q < 4; q++) acc[u][q] = 0.f;

    int4 av[4];   // adj prefetch: 256x32 ints / 512 thr = 4 int4

#define LOADG_ADJ(ch) do {                                                              \
        const int k0 = kbase + (ch) * KC;                                               \
        _Pragma("unroll")                                                               \
        for (int it = 0; it < 4; it++) {                                                \
            int idx = t + it * 512;                                                     \
            int r = idx >> 3, c4 = idx & 7;                                             \
            av[it] = *(const int4*)(adj + (size_t)(i0 + r) * NN + k0 + c4 * 4);         \
        }                                                                               \
    } while (0)

#define STS_ADJ(s) do {                                                                 \
        char* base = smem + (s) * STG + SA_OFF;                                         \
        _Pragma("unroll")                                                               \
        for (int it = 0; it < 4; it++) {                                                \
            int idx = t + it * 512;                                                     \
            int r = idx >> 3, c4 = idx & 7;                                             \
            uint32_t w0 = (av[it].x ? 0x3F80u : 0u) | ((av[it].y ? 0x3F80u : 0u) << 16);\
            uint32_t w1 = (av[it].z ? 0x3F80u : 0u) | ((av[it].w ? 0x3F80u : 0u) << 16);\
            *(uint2*)(base + SWZ64((uint32_t)(r * 64 + c4 * 8))) = make_uint2(w0, w1);  \
        }                                                                               \
    } while (0)

#define CPB(ch, s) do {                                                                 \
        const int k0 = kbase + (ch) * KC;                                               \
        const uint32_t bh = sb + (s) * STG + SH_OFF;                                    \
        const uint32_t bl = sb + (s) * STG + SL_OFF;                                    \
        _Pragma("unroll")                                                               \
        for (int it = 0; it < 2; it++) {                                                \
            int idx = t + it * 512;                                                     \
            if (idx < NP * 4) {                                                         \
                int n = idx >> 2, c = idx & 3;                                          \
                uint32_t sw = SWZ64((uint32_t)(n * 64 + c * 16));                       \
                CP_ASYNC16(bh + sw, (const char*)(g_Bhi + (size_t)n * NN + k0 + c * 8));\
                CP_ASYNC16(bl + sw, (const char*)(g_Blo + (size_t)n * NN + k0 + c * 8));\
            }                                                                           \
        }                                                                               \
    } while (0)

    // prologue: stage 0
    CPB(0, 0); CP_COMMIT();
    LOADG_ADJ(0); STS_ADJ(0);
    CP_WAIT0();
    __syncthreads();

    for (int ch = 0; ch < NCHUNK; ch++) {
        const int s = ch & 1;
        if (ch + 1 < NCHUNK) {
            LOADG_ADJ(ch + 1);
            CPB(ch + 1, s ^ 1); CP_COMMIT();
        }

        const uint32_t sA = sb + s * STG + SA_OFF;
        const uint32_t sH = sb + s * STG + SH_OFF;
        const uint32_t sL = sb + s * STG + SL_OFF;

#pragma unroll
        for (int q = 0; q < 2; q++) {
            uint32_t a0, a1, a2, a3, a4, a5, a6, a7;
            ldsm_x4(a0, a1, a2, a3,
                    sA + SWZ64((uint32_t)((mb + lm) * 64 + q * 32 + (l >> 4) * 16)));
            ldsm_x4(a4, a5, a6, a7,
                    sA + SWZ64((uint32_t)((mb + 16 + lm) * 64 + q * 32 + (l >> 4) * 16)));
#pragma unroll
            for (int p = 0; p < 4; p++) {
                uint32_t sw = SWZ64((uint32_t)((nb + p * 16 + brow) * 64 + q * 32 + bhalf * 16));
                uint32_t b0, b1, b2, b3;
                ldsm_x4(b0, b1, b2, b3, sH + sw);
                mma_bf16(acc[p * 2 + 0],     a0, a1, a2, a3, b0, b1);
                mma_bf16(acc[p * 2 + 1],     a0, a1, a2, a3, b2, b3);
                mma_bf16(acc[9 + p * 2 + 0], a4, a5, a6, a7, b0, b1);
                mma_bf16(acc[9 + p * 2 + 1], a4, a5, a6, a7, b2, b3);
                ldsm_x4(b0, b1, b2, b3, sL + sw);
                mma_bf16(acc[p * 2 + 0],     a0, a1, a2, a3, b0, b1);
                mma_bf16(acc[p * 2 + 1],     a0, a1, a2, a3, b2, b3);
                mma_bf16(acc[9 + p * 2 + 0], a4, a5, a6, a7, b0, b1);
                mma_bf16(acc[9 + p * 2 + 1], a4, a5, a6, a7, b2, b3);
            }
            {   // tail n-tile (8 cols)
                uint32_t sw = SWZ64((uint32_t)((nb + 64 + (lm & 7)) * 64 + q * 32 + (lm >> 3) * 16));
                uint32_t b0, b1;
                ldsm_x2(b0, b1, sH + sw);
                mma_bf16(acc[8],  a0, a1, a2, a3, b0, b1);
                mma_bf16(acc[17], a4, a5, a6, a7, b0, b1);
                ldsm_x2(b0, b1, sL + sw);
                mma_bf16(acc[8],  a0, a1, a2, a3, b0, b1);
                mma_bf16(acc[17], a4, a5, a6, a7, b0, b1);
            }
        }

        if (ch + 1 < NCHUNK) {
            STS_ADJ(s ^ 1);
            CP_WAIT0();
        }
        __syncthreads();
    }

    // epilogue: fp32 partials
    {
        float* dst = g_part + (size_t)blockIdx.x * MT * NP;
#pragma unroll
        for (int m = 0; m < 2; m++) {
            const int row0 = mb + m * 16 + (l >> 2);
#pragma unroll
            for (int nt = 0; nt < 9; nt++) {
                const int col = nb + nt * 8 + (l & 3) * 2;
                *(float2*)(dst + (size_t)row0 * NP + col) =
                    make_float2(acc[m * 9 + nt][0], acc[m * 9 + nt][1]);
                *(float2*)(dst + (size_t)(row0 + 8) * NP + col) =
                    make_float2(acc[m * 9 + nt][2], acc[m * 9 + nt][3]);
            }
        }
    }
#undef LOADG_ADJ
#undef STS_ADJ
#undef CPB
}

// ---------------- K3: combine K-split partials, divide by denominator ----------------
__global__ __launch_bounds__(128) void k3_finish(float* __restrict__ out) {
    const int i = blockIdx.x;           // node row
    const int n = threadIdx.x;          // output col 0..127
    const int mt = i >> 8, row = i & 255;
    float num = 0.f, den = 0.f;
#pragma unroll
    for (int ks = 0; ks < KSPLIT; ks++) {
        const float* p = g_part + ((size_t)(ks * NMT + mt) * MT + row) * NP;
        num += p[n];
        den += p[HD + (n >> 6)];
    }
    out[(size_t)i * HD + n] = num / den;
}

// ---------------- launch ----------------
extern "C" void kernel_launch(void* const* d_in, const int* in_sizes, int n_in,
                              void* d_out, int out_size) {
    (void)in_sizes; (void)n_in; (void)out_size;
    const float* x      = (const float*)d_in[0];
    const int*   adj    = (const int*)d_in[1];
    const float* W      = (const float*)d_in[2];
    // d_in[3] = attn_l: constant along the softmax axis -> cancels, unused
    const float* attn_r = (const float*)d_in[4];
    float* out = (float*)d_out;

    cudaFuncSetAttribute(k2_agg, cudaFuncAttributeMaxDynamicSharedMemorySize, SMEM_K2);

    k1_gemm<<<NN / 64, 256>>>(x, W);
    k1b_er<<<NN / 8, 256>>>(attn_r);
    k1b_buildB<<<NN / 64, 256>>>();
    k2_agg<<<KSPLIT * NMT, 512, SMEM_K2>>>(adj);
    k3_finish<<<NN, 128>>>(out);
}